// round 9
// baseline (speedup 1.0000x reference)
#include <cuda_runtime.h>
#include <cuda_bf16.h>
#include <cstdint>

#define NN      100000
#define NE      1600000
#define F       128
#define NREL    5
#define NN_PAD  100096          // 782 * 128
#define KTOT    768
#define BLAYER  98304           // 128 * 768 per-layer B elements
#define M5      (NN * NREL)
#define CSR_NB  120             // resident blocks for software grid sync

#if defined(__CUDA_ARCH_FEAT_SM103_ALL) || defined(__CUDA_ARCH_FEAT_SM100_ALL)
#define HAS_TCGEN05 1
#else
#define HAS_TCGEN05 0
#endif

// ---------------- device scratch (no allocations allowed) ----------------
// AG layout: [rel][node][512B block] = 128 bf16 hi (256B) then 128 bf16 lo (256B)
__device__ __align__(256) unsigned char g_AG[(size_t)NREL * NN_PAD * 512];
__device__ __align__(256) __nv_bfloat16 g_Bh[3 * BLAYER];   // weights hi [l][n][k]
__device__ __align__(256) __nv_bfloat16 g_Bl[3 * BLAYER];
__device__ float g_B1[(size_t)NN * F];
__device__ float g_B2[(size_t)NN * F];
__device__ int   g_deg5[M5];
__device__ int   g_off5[M5 + 1];
__device__ int   g_cur5[M5];
__device__ int   g_edges[NE];                 // src, sorted by (dst, rel)
__device__ int   g_bsums[512];
__device__ int   g_bar = 0;
__device__ volatile unsigned g_sense = 0;

// ---------------- small helpers ----------------
__device__ __forceinline__ uint32_t s2u(const void* p) {
    return (uint32_t)__cvta_generic_to_shared(p);
}
__device__ __forceinline__ void bsplit(float v, __nv_bfloat16& h, __nv_bfloat16& l) {
    h = __float2bfloat16_rn(v);
    l = __float2bfloat16_rn(v - __bfloat162float(h));
}
__device__ __forceinline__ void pack8(const float* f, uint4& hi, uint4& lo) {
    uint32_t h[4], l[4];
#pragma unroll
    for (int i = 0; i < 4; i++) {
        __nv_bfloat16 h0, l0, h1, l1;
        bsplit(f[2 * i], h0, l0);
        bsplit(f[2 * i + 1], h1, l1);
        __nv_bfloat162 hh = __halves2bfloat162(h0, h1);
        __nv_bfloat162 ll = __halves2bfloat162(l0, l1);
        h[i] = *(uint32_t*)&hh;
        l[i] = *(uint32_t*)&ll;
    }
    hi = make_uint4(h[0], h[1], h[2], h[3]);
    lo = make_uint4(l[0], l[1], l[2], l[3]);
}
__device__ __forceinline__ void mbar_init(uint32_t a, uint32_t cnt) {
    asm volatile("mbarrier.init.shared.b64 [%0], %1;" :: "r"(a), "r"(cnt) : "memory");
}
__device__ __forceinline__ void mbar_wait(uint32_t a, int par) {
    asm volatile(
        "{\n\t.reg .pred P;\n"
        "WL%=:\n\t"
        "mbarrier.try_wait.parity.acquire.cta.shared::cta.b64 P, [%0], %1, 0x989680;\n\t"
        "@P bra WD%=;\n\t"
        "bra WL%=;\n"
        "WD%=:\n\t}"
        :: "r"(a), "r"(par) : "memory");
}
__device__ __forceinline__ void gsync(int nb) {
    __syncthreads();
    if (threadIdx.x == 0) {
        unsigned s = g_sense;
        __threadfence();
        if (atomicAdd(&g_bar, 1) == nb - 1) {
            g_bar = 0;
            __threadfence();
            g_sense = s + 1;
        } else {
            while (g_sense == s) { }
        }
        __threadfence();
    }
    __syncthreads();
}

// ---------------- single-kernel CSR build: zero -> hist -> scan -> place ----------------
__global__ void __launch_bounds__(1024, 1) k_csr(
    const int* __restrict__ src, const int* __restrict__ dst,
    const int* __restrict__ et, int E, int m)
{
    const int NB = gridDim.x;
    int tid = threadIdx.x, bid = blockIdx.x;
    int gt = bid * 1024 + tid, gs = NB * 1024;
    __shared__ int sh[1024];

    for (int i = gt; i < m; i += gs) g_deg5[i] = 0;
    // zero AG rows for padded nodes (n..NN_PAD) so last-tile MMA reads zeros
    for (int r = 0; r < NREL; r++) {
        unsigned char* p = g_AG + ((size_t)r * NN_PAD + NN) * 512;
        size_t bytes = (size_t)(NN_PAD - NN) * 512;
        for (size_t i = (size_t)gt * 16; i + 16 <= bytes; i += (size_t)gs * 16)
            *(uint4*)(p + i) = make_uint4(0, 0, 0, 0);
    }
    gsync(NB);

    for (int e = gt; e < E; e += gs) atomicAdd(&g_deg5[dst[e] * NREL + et[e]], 1);
    gsync(NB);

    int RB = (m + NB - 1) / NB;
    int CH = (RB + 1023) / 1024;
    int base = bid * RB;
    int lim = min(base + RB, m);
    int i0 = base + tid * CH;
    int mysum = 0;
#pragma unroll 4
    for (int j = 0; j < CH; j++) {
        int i = i0 + j;
        if (i < lim) mysum += g_deg5[i];
    }
    sh[tid] = mysum;
    __syncthreads();
    for (int d = 1; d < 1024; d <<= 1) {
        int t = (tid >= d) ? sh[tid - d] : 0;
        __syncthreads();
        sh[tid] += t;
        __syncthreads();
    }
    if (tid == 1023) g_bsums[bid] = sh[1023];
    int myoff_local = sh[tid] - mysum;
    gsync(NB);

    if (bid == 0) {
        int v = (tid < NB) ? g_bsums[tid] : 0;
        sh[tid] = v;
        __syncthreads();
        for (int d = 1; d < 1024; d <<= 1) {
            int t = (tid >= d) ? sh[tid - d] : 0;
            __syncthreads();
            sh[tid] += t;
            __syncthreads();
        }
        if (tid < NB) g_bsums[tid] = sh[tid] - v;
    }
    gsync(NB);

    int run = g_bsums[bid] + myoff_local;
#pragma unroll 4
    for (int j = 0; j < CH; j++) {
        int i = i0 + j;
        if (i < lim) {
            g_off5[i] = run;
            g_cur5[i] = run;
            run += g_deg5[i];
        }
    }
    if (gt == 0) g_off5[m] = E;
    gsync(NB);

    for (int e = gt; e < E; e += gs) {
        int b = dst[e] * NREL + et[e];
        int pos = atomicAdd(&g_cur5[b], 1);
        g_edges[pos] = src[e];
    }
}

// ---------------- weights -> transposed bf16 hi/lo B matrices ----------------
__global__ void k_prepB(const float* __restrict__ W1, const float* __restrict__ r1,
                        const float* __restrict__ W2, const float* __restrict__ r2,
                        const float* __restrict__ W3, const float* __restrict__ r3) {
    int idx = blockIdx.x * blockDim.x + threadIdx.x;
    if (idx >= 3 * BLAYER) return;
    int l = idx / BLAYER;
    int rem = idx % BLAYER;
    int nn = rem / KTOT;
    int k = rem % KTOT;
    const float* Wl = (l == 0) ? W1 : ((l == 1) ? W2 : W3);
    const float* rl = (l == 0) ? r1 : ((l == 1) ? r2 : r3);
    float v = (k < 128) ? rl[k * 128 + nn] : Wl[(size_t)(k - 128) * 128 + nn];
    __nv_bfloat16 h, lo;
    bsplit(v, h, lo);
    g_Bh[idx] = h;
    g_Bl[idx] = lo;
}

// ---------------- gather: one warp per (node, rel) bucket ----------------
__global__ void k_gather(const float* __restrict__ X, int n) {
    int b = (blockIdx.x * blockDim.x + threadIdx.x) >> 5;
    if (b >= n * NREL) return;
    int lane = threadIdx.x & 31;
    int beg = g_off5[b], end = g_off5[b + 1];
    int node = b / NREL, rel = b - node * NREL;

    float ax = 0.f, ay = 0.f, az = 0.f, aw = 0.f;
    int e = beg;
    for (; e + 4 <= end; e += 4) {
        int s0 = __ldg(&g_edges[e]);
        int s1 = __ldg(&g_edges[e + 1]);
        int s2 = __ldg(&g_edges[e + 2]);
        int s3 = __ldg(&g_edges[e + 3]);
        float4 v0 = __ldg((const float4*)X + (size_t)s0 * 32 + lane);
        float4 v1 = __ldg((const float4*)X + (size_t)s1 * 32 + lane);
        float4 v2 = __ldg((const float4*)X + (size_t)s2 * 32 + lane);
        float4 v3 = __ldg((const float4*)X + (size_t)s3 * 32 + lane);
        ax += (v0.x + v1.x) + (v2.x + v3.x);
        ay += (v0.y + v1.y) + (v2.y + v3.y);
        az += (v0.z + v1.z) + (v2.z + v3.z);
        aw += (v0.w + v1.w) + (v2.w + v3.w);
    }
    for (; e < end; e++) {
        int s0 = __ldg(&g_edges[e]);
        float4 v0 = __ldg((const float4*)X + (size_t)s0 * 32 + lane);
        ax += v0.x; ay += v0.y; az += v0.z; aw += v0.w;
    }
    int cnt = end - beg;
    float sc = cnt ? 1.f / (float)cnt : 0.f;
    float f0 = ax * sc, f1 = ay * sc, f2 = az * sc, f3 = aw * sc;

    __nv_bfloat16 h0, l0, h1, l1, h2, l2, h3, l3;
    bsplit(f0, h0, l0); bsplit(f1, h1, l1);
    bsplit(f2, h2, l2); bsplit(f3, h3, l3);
    __nv_bfloat162 hA = __halves2bfloat162(h0, h1);
    __nv_bfloat162 hB = __halves2bfloat162(h2, h3);
    __nv_bfloat162 lA = __halves2bfloat162(l0, l1);
    __nv_bfloat162 lB = __halves2bfloat162(l2, l3);
    // contiguous 512B block per bucket: hi[256B] | lo[256B]
    unsigned char* base = g_AG + ((size_t)rel * NN_PAD + node) * 512;
    *(uint2*)(base + lane * 8)       = make_uint2(*(uint32_t*)&hA, *(uint32_t*)&hB);
    *(uint2*)(base + 256 + lane * 8) = make_uint2(*(uint32_t*)&lA, *(uint32_t*)&lB);
}

// ---------------- tcgen05 fused GEMM ----------------
// Y = relu([X | A0..A4] @ Bt + bias), 3-term bf16 split, 12 K-chunks of 64.
// 3-stage pipeline; MMA-completion wait overlapped with chunk processing.
#define SMEM_TILES  1024
#define STAGE_BYTES 65536       // Ah(16K) Al(16K) Bh(16K) Bl(16K)
#define SMEM_TOTAL  (SMEM_TILES + 3 * STAGE_BYTES)
#define MMA_IDESC   ((1u << 4) | (1u << 7) | (1u << 10) | (16u << 17) | (8u << 24))

#if HAS_TCGEN05
__device__ __forceinline__ uint64_t sdesc(uint32_t a) {
    // SW128, version=1 (Blackwell), SBO=64, LBO=1 (K-major, 128B rows)
    return 0x4000404000010000ULL | (uint64_t)((a >> 4) & 0x3FFF);
}
__device__ __forceinline__ void mma_f16_ss(uint32_t d, uint64_t ad, uint64_t bd,
                                           uint32_t idesc, uint32_t en) {
    asm volatile(
        "{\n\t.reg .pred p;\n\t"
        "setp.ne.u32 p, %4, 0;\n\t"
        "tcgen05.mma.cta_group::1.kind::f16 [%0], %1, %2, %3, {%5, %5, %5, %5}, p;\n\t}"
        :: "r"(d), "l"(ad), "l"(bd), "r"(idesc), "r"(en), "r"(0u) : "memory");
}
__device__ __forceinline__ void mma_commit(uint32_t mbar) {
    asm volatile(
        "tcgen05.commit.cta_group::1.mbarrier::arrive::one.shared::cluster.b64 [%0];"
        :: "r"(mbar) : "memory");
}
#define LDTM_X32(r, addr)                                                        \
    asm volatile(                                                                \
        "tcgen05.ld.sync.aligned.32x32b.x32.b32 "                                \
        "{%0, %1, %2, %3, %4, %5, %6, %7, "                                      \
        " %8, %9, %10, %11, %12, %13, %14, %15, "                                \
        " %16, %17, %18, %19, %20, %21, %22, %23, "                              \
        " %24, %25, %26, %27, %28, %29, %30, %31}, [%32];"                       \
        : "=r"((r)[0]),  "=r"((r)[1]),  "=r"((r)[2]),  "=r"((r)[3]),             \
          "=r"((r)[4]),  "=r"((r)[5]),  "=r"((r)[6]),  "=r"((r)[7]),             \
          "=r"((r)[8]),  "=r"((r)[9]),  "=r"((r)[10]), "=r"((r)[11]),            \
          "=r"((r)[12]), "=r"((r)[13]), "=r"((r)[14]), "=r"((r)[15]),            \
          "=r"((r)[16]), "=r"((r)[17]), "=r"((r)[18]), "=r"((r)[19]),            \
          "=r"((r)[20]), "=r"((r)[21]), "=r"((r)[22]), "=r"((r)[23]),            \
          "=r"((r)[24]), "=r"((r)[25]), "=r"((r)[26]), "=r"((r)[27]),            \
          "=r"((r)[28]), "=r"((r)[29]), "=r"((r)[30]), "=r"((r)[31])             \
        : "r"(addr))

// chunks 0,1: A from f32 X (LDG+split+STS), B via cp.async.
// chunks 2..11: A from contiguous AG blocks: rel=(c-2)>>1, half=(c-2)&1.
__device__ __forceinline__ void load_chunk(
    int c, char* smem, uint32_t stageOff, int m0, int tid,
    const float* __restrict__ X,
    const __nv_bfloat16* __restrict__ Bh, const __nv_bfloat16* __restrict__ Bl, int n)
{
    uint32_t sbase = s2u(smem) + stageOff;
    if (c < 2) {
#pragma unroll
        for (int i = 0; i < 8; i++) {
            int idx = tid + i * 256;
            int q = idx >> 10, j = idx & 1023;
            int row = j >> 3, s16 = j & 7;
            uint32_t byte = row * 128 + s16 * 16;
            uint32_t dstp = sbase + 32768 + q * 16384 + (byte ^ ((byte >> 3) & 0x70));
            const char* srcp = (const char*)(q ? Bl : Bh) + (size_t)row * 1536 + c * 128 + s16 * 16;
            asm volatile("cp.async.cg.shared.global [%0], [%1], 16;" :: "r"(dstp), "l"(srcp));
        }
        asm volatile("cp.async.commit_group;" ::: "memory");
        int row = tid >> 1, h = tid & 1;
        int node = m0 + row;
        const float* xr = X + (size_t)node * 128 + c * 64 + h * 32;
#pragma unroll
        for (int j = 0; j < 4; j++) {
            float v[8];
            if (node < n) {
                float4 f0 = __ldg((const float4*)(xr + j * 8));
                float4 f1 = __ldg((const float4*)(xr + j * 8) + 1);
                v[0] = f0.x; v[1] = f0.y; v[2] = f0.z; v[3] = f0.w;
                v[4] = f1.x; v[5] = f1.y; v[6] = f1.z; v[7] = f1.w;
            } else {
#pragma unroll
                for (int q = 0; q < 8; q++) v[q] = 0.f;
            }
            uint4 hi, lo;
            pack8(v, hi, lo);
            uint32_t byte = row * 128 + h * 64 + j * 16;
            uint32_t sw = byte ^ ((byte >> 3) & 0x70);
            *(uint4*)(smem + stageOff + sw) = hi;
            *(uint4*)(smem + stageOff + 16384 + sw) = lo;
        }
    } else {
        int rc = (c - 2) >> 1;                 // relation 0..4
        int half = (c - 2) & 1;                // 0: cols 0-63, 1: cols 64-127
        const unsigned char* agbase =
            g_AG + ((size_t)rc * NN_PAD + m0) * 512 + half * 128;
#pragma unroll
        for (int i = 0; i < 16; i++) {
            int idx = tid + i * 256;
            int sub = idx >> 10, j = idx & 1023;
            int row = j >> 3, s16 = j & 7;
            uint32_t byte = row * 128 + s16 * 16;
            uint32_t dstp = sbase + sub * 16384 + (byte ^ ((byte >> 3) & 0x70));
            const char* srcp;
            if (sub == 0)      srcp = (const char*)agbase + (size_t)row * 512 + s16 * 16;
            else if (sub == 1) srcp = (const char*)agbase + (size_t)row * 512 + 256 + s16 * 16;
            else if (sub == 2) srcp = (const char*)Bh + (size_t)row * 1536 + c * 128 + s16 * 16;
            else               srcp = (const char*)Bl + (size_t)row * 1536 + c * 128 + s16 * 16;
            asm volatile("cp.async.cg.shared.global [%0], [%1], 16;" :: "r"(dstp), "l"(srcp));
        }
        asm volatile("cp.async.commit_group;" ::: "memory");
    }
}
#endif  // HAS_TCGEN05

__global__ void __launch_bounds__(256, 1) k_mma(
    const float* __restrict__ X,
    const __nv_bfloat16* __restrict__ Bh, const __nv_bfloat16* __restrict__ Bl,
    const float* __restrict__ bias, float* __restrict__ Y, int n)
{
#if HAS_TCGEN05
    extern __shared__ char smem[];
    uint32_t sb = s2u(smem);
    int tid = threadIdx.x;
    int wid = tid >> 5, lane = tid & 31;
    int m0 = blockIdx.x * 128;

    if (wid == 0) {
        asm volatile(
            "tcgen05.alloc.cta_group::1.sync.aligned.shared::cta.b32 [%0], %1;"
            :: "r"(sb), "r"(128u) : "memory");
        asm volatile("tcgen05.relinquish_alloc_permit.cta_group::1.sync.aligned;");
    }
    if (tid == 0) {
        mbar_init(sb + 16, 1);
        mbar_init(sb + 24, 1);
        mbar_init(sb + 32, 1);
    }
    __syncthreads();
    uint32_t tmem;
    asm volatile("ld.shared.b32 %0, [%1];" : "=r"(tmem) : "r"(sb));

    load_chunk(0, smem, SMEM_TILES + 0 * STAGE_BYTES, m0, tid, X, Bh, Bl, n);
    load_chunk(1, smem, SMEM_TILES + 1 * STAGE_BYTES, m0, tid, X, Bh, Bl, n);

#pragma unroll
    for (int c = 0; c < 12; c++) {
        // 1) chunk c's data ready (loads issued >=2 iterations ago)
        if (c <= 10) asm volatile("cp.async.wait_group 1;" ::: "memory");
        else         asm volatile("cp.async.wait_group 0;" ::: "memory");
        __syncthreads();
        // 2) issue MMA c immediately (tensor queues behind MMA c-1)
        if (tid == 0) {
            asm volatile("fence.proxy.async.shared::cta;" ::: "memory");
            uint32_t tb = sb + SMEM_TILES + (c % 3) * STAGE_BYTES;
            uint64_t dAh = sdesc(tb);
            uint64_t dAl = sdesc(tb + 16384);
            uint64_t dBh = sdesc(tb + 32768);
            uint64_t dBl = sdesc(tb + 49152);
#pragma unroll
            for (int ks = 0; ks < 4; ks++) {
                uint32_t e0 = (c == 0 && ks == 0) ? 0u : 1u;
                mma_f16_ss(tmem, dAh + ks * 2, dBh + ks * 2, MMA_IDESC, e0);
                mma_f16_ss(tmem, dAh + ks * 2, dBl + ks * 2, MMA_IDESC, 1u);
                mma_f16_ss(tmem, dAl + ks * 2, dBh + ks * 2, MMA_IDESC, 1u);
            }
            mma_commit(sb + 16 + (c % 3) * 8);
        }
        // 3) wait for MMA c-1 (committed a full iteration ago -> nearly free),
        //    freeing buffer (c+2)%3 for the next loads
        if (c >= 1) {
            int t = c - 1;
            mbar_wait(sb + 16 + (t % 3) * 8, (t / 3) & 1);
        }
        // 4) issue loads for chunk c+2 into the just-freed buffer
        if (c + 2 < 12)
            load_chunk(c + 2, smem, SMEM_TILES + ((c + 2) % 3) * STAGE_BYTES,
                       m0, tid, X, Bh, Bl, n);
    }
    // final: MMA 11 on mbar (11%3)=2, 4th event -> parity 1
    mbar_wait(sb + 32, 1);
    asm volatile("tcgen05.fence::after_thread_sync;" ::: "memory");

    // ---- epilogue: TMEM -> bias+relu -> SMEM transpose -> coalesced f32 stores ----
    float* smF = (float*)(smem + SMEM_TILES);   // [128][129] f32
    int sp = wid & 3, hh = wid >> 2;
#pragma unroll
    for (int p = 0; p < 2; p++) {
        uint32_t r[32];
        LDTM_X32(r, tmem + hh * 64 + p * 32);
        asm volatile("tcgen05.wait::ld.sync.aligned;" ::: "memory");
        int cb = hh * 64 + p * 32;
#pragma unroll
        for (int j = 0; j < 32; j++) {
            float v = __uint_as_float(r[j]) + __ldg(&bias[cb + j]);
            smF[(sp * 32 + lane) * 129 + cb + j] = fmaxf(v, 0.f);
        }
    }
    __syncthreads();
    for (int idx = tid; idx < 4096; idx += 256) {
        int row = idx >> 5, q = idx & 31;
        int grow = m0 + row;
        if (grow < n) {
            float* s = &smF[row * 129 + q * 4];
            float4 o;
            o.x = s[0]; o.y = s[1]; o.z = s[2]; o.w = s[3];
            *(float4*)(Y + (size_t)grow * 128 + q * 4) = o;
        }
    }
    __syncthreads();
    if (wid == 0) {
        asm volatile(
            "tcgen05.dealloc.cta_group::1.sync.aligned.b32 %0, %1;"
            :: "r"(tmem), "r"(128u));
    }
#else
    // ---- fallback (family-generic PTX pass; never used when sm_103a SASS loads) ----
    int tid = threadIdx.x;
    int m0 = blockIdx.x * 128;
    for (int o = tid; o < 128 * 128; o += 256) {
        int row = m0 + (o >> 7), col = o & 127;
        if (row >= n) continue;
        float acc = bias[col];
        for (int k = 0; k < 128; k++) {
            float b = __bfloat162float(Bh[(size_t)col * KTOT + k]) +
                      __bfloat162float(Bl[(size_t)col * KTOT + k]);
            acc += X[(size_t)row * 128 + k] * b;
        }
        for (int r = 0; r < NREL; r++) {
            const unsigned char* base = g_AG + ((size_t)r * NN_PAD + row) * 512;
            const __nv_bfloat16* ph = (const __nv_bfloat16*)base;
            const __nv_bfloat16* pl = (const __nv_bfloat16*)(base + 256);
            for (int k = 0; k < 128; k++) {
                float a = __bfloat162float(ph[k]) + __bfloat162float(pl[k]);
                float b = __bfloat162float(Bh[(size_t)col * KTOT + 128 + r * 128 + k]) +
                          __bfloat162float(Bl[(size_t)col * KTOT + 128 + r * 128 + k]);
                acc += a * b;
            }
        }
        Y[(size_t)row * 128 + col] = fmaxf(acc, 0.f);
    }
#endif
}

// ---------------- launch ----------------
extern "C" void kernel_launch(void* const* d_in, const int* in_sizes, int n_in,
                              void* d_out, int out_size) {
    const float* x  = (const float*)d_in[0];
    const int*   ei = (const int*)d_in[1];
    const int*   et = (const int*)d_in[2];
    const float* W1 = (const float*)d_in[3];
    const float* r1 = (const float*)d_in[4];
    const float* b1 = (const float*)d_in[5];
    const float* W2 = (const float*)d_in[6];
    const float* r2 = (const float*)d_in[7];
    const float* b2 = (const float*)d_in[8];
    const float* W3 = (const float*)d_in[9];
    const float* r3 = (const float*)d_in[10];
    const float* b3 = (const float*)d_in[11];
    float* out = (float*)d_out;

    int n = in_sizes[0] / F;
    int E = in_sizes[1] / 2;
    const int* src = ei;
    const int* dst = ei + E;
    int m = n * NREL;

    float *pB1, *pB2;
    __nv_bfloat16 *pBh, *pBl;
    cudaGetSymbolAddress((void**)&pB1, g_B1);
    cudaGetSymbolAddress((void**)&pB2, g_B2);
    cudaGetSymbolAddress((void**)&pBh, g_Bh);
    cudaGetSymbolAddress((void**)&pBl, g_Bl);

    static int smem_set = 0;
    if (!smem_set) {
        cudaFuncSetAttribute(k_mma, cudaFuncAttributeMaxDynamicSharedMemorySize, SMEM_TOTAL);
        smem_set = 1;
    }

    int gb = (m * 32 + 255) / 256;       // one warp per (node, rel) bucket
    int mb = (n + 127) / 128;

    k_csr<<<CSR_NB, 1024>>>(src, dst, et, E, m);
    k_prepB<<<(3 * BLAYER + 255) / 256, 256>>>(W1, r1, W2, r2, W3, r3);
    // layer 1  (k_mma is 4th launch -> ncu capture target)
    k_gather<<<gb, 256>>>(x, n);
    k_mma<<<mb, 256, SMEM_TOTAL>>>(x, pBh, pBl, b1, pB1, n);
    // layer 2
    k_gather<<<gb, 256>>>(pB1, n);
    k_mma<<<mb, 256, SMEM_TOTAL>>>(pB1, pBh + BLAYER, pBl + BLAYER, b2, pB2, n);
    // layer 3
    k_gather<<<gb, 256>>>(pB2, n);
    k_mma<<<mb, 256, SMEM_TOTAL>>>(pB2, pBh + 2 * BLAYER, pBl + 2 * BLAYER, b3, out, n);
}

// round 10
// speedup vs baseline: 1.0649x; 1.0649x over previous
#include <cuda_runtime.h>
#include <cuda_bf16.h>
#include <cstdint>

#define NN      100000
#define NE      1600000
#define F       128
#define NREL    5
#define NN_PAD  100096          // 782 * 128
#define KTOT    768
#define BLAYER  98304           // 128 * 768 per-layer B elements
#define M5      (NN * NREL)
#define CSR_NB  120             // resident blocks for software grid sync

#if defined(__CUDA_ARCH_FEAT_SM103_ALL) || defined(__CUDA_ARCH_FEAT_SM100_ALL)
#define HAS_TCGEN05 1
#else
#define HAS_TCGEN05 0
#endif

// ---------------- device scratch (no allocations allowed) ----------------
// AG layout: [rel][node][512B block] = 128 bf16 hi (256B) then 128 bf16 lo (256B)
__device__ __align__(256) unsigned char g_AG[(size_t)NREL * NN_PAD * 512];
__device__ __align__(256) __nv_bfloat16 g_Bh[3 * BLAYER];   // weights hi [l][n][k]
__device__ __align__(256) __nv_bfloat16 g_Bl[3 * BLAYER];
__device__ float g_B1[(size_t)NN * F];
__device__ float g_B2[(size_t)NN * F];
__device__ int   g_deg5[M5];
__device__ int   g_off5[M5 + 1];
__device__ int   g_cur5[M5];
__device__ int   g_edges[NE];                 // src, sorted by (dst, rel)
__device__ int   g_bsums[512];
__device__ int   g_bar = 0;
__device__ volatile unsigned g_sense = 0;

// ---------------- small helpers ----------------
__device__ __forceinline__ uint32_t s2u(const void* p) {
    return (uint32_t)__cvta_generic_to_shared(p);
}
__device__ __forceinline__ void bsplit(float v, __nv_bfloat16& h, __nv_bfloat16& l) {
    h = __float2bfloat16_rn(v);
    l = __float2bfloat16_rn(v - __bfloat162float(h));
}
__device__ __forceinline__ void pack8(const float* f, uint4& hi, uint4& lo) {
    uint32_t h[4], l[4];
#pragma unroll
    for (int i = 0; i < 4; i++) {
        __nv_bfloat16 h0, l0, h1, l1;
        bsplit(f[2 * i], h0, l0);
        bsplit(f[2 * i + 1], h1, l1);
        __nv_bfloat162 hh = __halves2bfloat162(h0, h1);
        __nv_bfloat162 ll = __halves2bfloat162(l0, l1);
        h[i] = *(uint32_t*)&hh;
        l[i] = *(uint32_t*)&ll;
    }
    hi = make_uint4(h[0], h[1], h[2], h[3]);
    lo = make_uint4(l[0], l[1], l[2], l[3]);
}
__device__ __forceinline__ void mbar_init(uint32_t a, uint32_t cnt) {
    asm volatile("mbarrier.init.shared.b64 [%0], %1;" :: "r"(a), "r"(cnt) : "memory");
}
__device__ __forceinline__ void mbar_wait(uint32_t a, int par) {
    asm volatile(
        "{\n\t.reg .pred P;\n"
        "WL%=:\n\t"
        "mbarrier.try_wait.parity.acquire.cta.shared::cta.b64 P, [%0], %1, 0x989680;\n\t"
        "@P bra WD%=;\n\t"
        "bra WL%=;\n"
        "WD%=:\n\t}"
        :: "r"(a), "r"(par) : "memory");
}
__device__ __forceinline__ void gsync(int nb) {
    __syncthreads();
    if (threadIdx.x == 0) {
        unsigned s = g_sense;
        __threadfence();
        if (atomicAdd(&g_bar, 1) == nb - 1) {
            g_bar = 0;
            __threadfence();
            g_sense = s + 1;
        } else {
            while (g_sense == s) { }
        }
        __threadfence();
    }
    __syncthreads();
}

// ---------------- single-kernel CSR build: zero -> hist -> scan -> place ----------------
__global__ void __launch_bounds__(1024, 1) k_csr(
    const int* __restrict__ src, const int* __restrict__ dst,
    const int* __restrict__ et, int E, int m)
{
    const int NB = gridDim.x;
    int tid = threadIdx.x, bid = blockIdx.x;
    int gt = bid * 1024 + tid, gs = NB * 1024;
    __shared__ int sh[1024];

    for (int i = gt; i < m; i += gs) g_deg5[i] = 0;
    // zero AG rows for padded nodes (n..NN_PAD) so last-tile MMA reads zeros
    for (int r = 0; r < NREL; r++) {
        unsigned char* p = g_AG + ((size_t)r * NN_PAD + NN) * 512;
        size_t bytes = (size_t)(NN_PAD - NN) * 512;
        for (size_t i = (size_t)gt * 16; i + 16 <= bytes; i += (size_t)gs * 16)
            *(uint4*)(p + i) = make_uint4(0, 0, 0, 0);
    }
    gsync(NB);

    for (int e = gt; e < E; e += gs) atomicAdd(&g_deg5[dst[e] * NREL + et[e]], 1);
    gsync(NB);

    int RB = (m + NB - 1) / NB;
    int CH = (RB + 1023) / 1024;
    int base = bid * RB;
    int lim = min(base + RB, m);
    int i0 = base + tid * CH;
    int mysum = 0;
#pragma unroll 4
    for (int j = 0; j < CH; j++) {
        int i = i0 + j;
        if (i < lim) mysum += g_deg5[i];
    }
    sh[tid] = mysum;
    __syncthreads();
    for (int d = 1; d < 1024; d <<= 1) {
        int t = (tid >= d) ? sh[tid - d] : 0;
        __syncthreads();
        sh[tid] += t;
        __syncthreads();
    }
    if (tid == 1023) g_bsums[bid] = sh[1023];
    int myoff_local = sh[tid] - mysum;
    gsync(NB);

    if (bid == 0) {
        int v = (tid < NB) ? g_bsums[tid] : 0;
        sh[tid] = v;
        __syncthreads();
        for (int d = 1; d < 1024; d <<= 1) {
            int t = (tid >= d) ? sh[tid - d] : 0;
            __syncthreads();
            sh[tid] += t;
            __syncthreads();
        }
        if (tid < NB) g_bsums[tid] = sh[tid] - v;
    }
    gsync(NB);

    int run = g_bsums[bid] + myoff_local;
#pragma unroll 4
    for (int j = 0; j < CH; j++) {
        int i = i0 + j;
        if (i < lim) {
            g_off5[i] = run;
            g_cur5[i] = run;
            run += g_deg5[i];
        }
    }
    if (gt == 0) g_off5[m] = E;
    gsync(NB);

    for (int e = gt; e < E; e += gs) {
        int b = dst[e] * NREL + et[e];
        int pos = atomicAdd(&g_cur5[b], 1);
        g_edges[pos] = src[e];
    }
}

// ---------------- weights -> transposed bf16 hi/lo B matrices ----------------
__global__ void k_prepB(const float* __restrict__ W1, const float* __restrict__ r1,
                        const float* __restrict__ W2, const float* __restrict__ r2,
                        const float* __restrict__ W3, const float* __restrict__ r3) {
    int idx = blockIdx.x * blockDim.x + threadIdx.x;
    if (idx >= 3 * BLAYER) return;
    int l = idx / BLAYER;
    int rem = idx % BLAYER;
    int nn = rem / KTOT;
    int k = rem % KTOT;
    const float* Wl = (l == 0) ? W1 : ((l == 1) ? W2 : W3);
    const float* rl = (l == 0) ? r1 : ((l == 1) ? r2 : r3);
    float v = (k < 128) ? rl[k * 128 + nn] : Wl[(size_t)(k - 128) * 128 + nn];
    __nv_bfloat16 h, lo;
    bsplit(v, h, lo);
    g_Bh[idx] = h;
    g_Bl[idx] = lo;
}

// ---------------- gather: one warp per (node, rel) bucket ----------------
__global__ void k_gather(const float* __restrict__ X, int n) {
    int b = (blockIdx.x * blockDim.x + threadIdx.x) >> 5;
    if (b >= n * NREL) return;
    int lane = threadIdx.x & 31;
    int beg = g_off5[b], end = g_off5[b + 1];
    int node = b / NREL, rel = b - node * NREL;

    float ax = 0.f, ay = 0.f, az = 0.f, aw = 0.f;
    int e = beg;
    for (; e + 4 <= end; e += 4) {
        int s0 = __ldg(&g_edges[e]);
        int s1 = __ldg(&g_edges[e + 1]);
        int s2 = __ldg(&g_edges[e + 2]);
        int s3 = __ldg(&g_edges[e + 3]);
        float4 v0 = __ldg((const float4*)X + (size_t)s0 * 32 + lane);
        float4 v1 = __ldg((const float4*)X + (size_t)s1 * 32 + lane);
        float4 v2 = __ldg((const float4*)X + (size_t)s2 * 32 + lane);
        float4 v3 = __ldg((const float4*)X + (size_t)s3 * 32 + lane);
        ax += (v0.x + v1.x) + (v2.x + v3.x);
        ay += (v0.y + v1.y) + (v2.y + v3.y);
        az += (v0.z + v1.z) + (v2.z + v3.z);
        aw += (v0.w + v1.w) + (v2.w + v3.w);
    }
    for (; e < end; e++) {
        int s0 = __ldg(&g_edges[e]);
        float4 v0 = __ldg((const float4*)X + (size_t)s0 * 32 + lane);
        ax += v0.x; ay += v0.y; az += v0.z; aw += v0.w;
    }
    int cnt = end - beg;
    float sc = cnt ? 1.f / (float)cnt : 0.f;
    float f0 = ax * sc, f1 = ay * sc, f2 = az * sc, f3 = aw * sc;

    __nv_bfloat16 h0, l0, h1, l1, h2, l2, h3, l3;
    bsplit(f0, h0, l0); bsplit(f1, h1, l1);
    bsplit(f2, h2, l2); bsplit(f3, h3, l3);
    __nv_bfloat162 hA = __halves2bfloat162(h0, h1);
    __nv_bfloat162 hB = __halves2bfloat162(h2, h3);
    __nv_bfloat162 lA = __halves2bfloat162(l0, l1);
    __nv_bfloat162 lB = __halves2bfloat162(l2, l3);
    // contiguous 512B block per bucket: hi[256B] | lo[256B]
    unsigned char* base = g_AG + ((size_t)rel * NN_PAD + node) * 512;
    *(uint2*)(base + lane * 8)       = make_uint2(*(uint32_t*)&hA, *(uint32_t*)&hB);
    *(uint2*)(base + 256 + lane * 8) = make_uint2(*(uint32_t*)&lA, *(uint32_t*)&lB);
}

// ---------------- tcgen05 fused GEMM ----------------
// Y = relu([X | A0..A4] @ Bt + bias), 3-term bf16 split.
// 24 K-chunks of 32; SW64 tiles (128 rows x 64B); 3 stages of 32KB -> 2 CTAs/SM.
#define SMEM_TILES  1024
#define STAGE_BYTES 32768       // Ah(8K) Al(8K) Bh(8K) Bl(8K)
#define SMEM_TOTAL  (SMEM_TILES + 3 * STAGE_BYTES)
#define NCHUNK      24
#define MMA_IDESC   ((1u << 4) | (1u << 7) | (1u << 10) | (16u << 17) | (8u << 24))

#if HAS_TCGEN05
__device__ __forceinline__ uint64_t sdesc64(uint32_t a) {
    // SW64 (layout=4), version=1 (Blackwell), SBO=32, LBO=1 (K-major, 64B rows)
    return ((uint64_t)4 << 61) | ((uint64_t)1 << 46) | ((uint64_t)32 << 32) |
           ((uint64_t)1 << 16) | (uint64_t)((a >> 4) & 0x3FFF);
}
__device__ __forceinline__ void mma_f16_ss(uint32_t d, uint64_t ad, uint64_t bd,
                                           uint32_t idesc, uint32_t en) {
    asm volatile(
        "{\n\t.reg .pred p;\n\t"
        "setp.ne.u32 p, %4, 0;\n\t"
        "tcgen05.mma.cta_group::1.kind::f16 [%0], %1, %2, %3, {%5, %5, %5, %5}, p;\n\t}"
        :: "r"(d), "l"(ad), "l"(bd), "r"(idesc), "r"(en), "r"(0u) : "memory");
}
__device__ __forceinline__ void mma_commit(uint32_t mbar) {
    asm volatile(
        "tcgen05.commit.cta_group::1.mbarrier::arrive::one.shared::cluster.b64 [%0];"
        :: "r"(mbar) : "memory");
}
#define LDTM_X32(r, addr)                                                        \
    asm volatile(                                                                \
        "tcgen05.ld.sync.aligned.32x32b.x32.b32 "                                \
        "{%0, %1, %2, %3, %4, %5, %6, %7, "                                      \
        " %8, %9, %10, %11, %12, %13, %14, %15, "                                \
        " %16, %17, %18, %19, %20, %21, %22, %23, "                              \
        " %24, %25, %26, %27, %28, %29, %30, %31}, [%32];"                       \
        : "=r"((r)[0]),  "=r"((r)[1]),  "=r"((r)[2]),  "=r"((r)[3]),             \
          "=r"((r)[4]),  "=r"((r)[5]),  "=r"((r)[6]),  "=r"((r)[7]),             \
          "=r"((r)[8]),  "=r"((r)[9]),  "=r"((r)[10]), "=r"((r)[11]),            \
          "=r"((r)[12]), "=r"((r)[13]), "=r"((r)[14]), "=r"((r)[15]),            \
          "=r"((r)[16]), "=r"((r)[17]), "=r"((r)[18]), "=r"((r)[19]),            \
          "=r"((r)[20]), "=r"((r)[21]), "=r"((r)[22]), "=r"((r)[23]),            \
          "=r"((r)[24]), "=r"((r)[25]), "=r"((r)[26]), "=r"((r)[27]),            \
          "=r"((r)[28]), "=r"((r)[29]), "=r"((r)[30]), "=r"((r)[31])             \
        : "r"(addr))

// chunks 0..3: A from f32 X (LDG+split+STS), B via cp.async.
// chunks 4..23: A from AG: rel=(c-4)>>2, quarter=(c-4)&3. All tiles SW64.
__device__ __forceinline__ void load_chunk(
    int c, char* smem, uint32_t stageOff, int m0, int tid,
    const float* __restrict__ X,
    const __nv_bfloat16* __restrict__ Bh, const __nv_bfloat16* __restrict__ Bl, int n)
{
    uint32_t sbase = s2u(smem) + stageOff;
    if (c < 4) {
        // B tiles via cp.async: 2 tiles x 512 units of 16B = 1024 units, 4/thread
#pragma unroll
        for (int i = 0; i < 4; i++) {
            int idx = tid + i * 256;
            int q = idx >> 9, j = idx & 511;
            int row = j >> 2, s16 = j & 3;
            uint32_t byte = row * 64 + s16 * 16;
            uint32_t dstp = sbase + 16384 + q * 8192 + (byte ^ ((byte >> 3) & 0x30));
            const char* srcp = (const char*)(q ? Bl : Bh) + (size_t)row * 1536 + c * 64 + s16 * 16;
            asm volatile("cp.async.cg.shared.global [%0], [%1], 16;" :: "r"(dstp), "l"(srcp));
        }
        asm volatile("cp.async.commit_group;" ::: "memory");
        // A tiles: f32 X -> bf16 hi/lo split -> swizzled STS (16 cols per thread)
        int row = tid >> 1, h = tid & 1;
        int node = m0 + row;
        const float* xr = X + (size_t)node * 128 + c * 32 + h * 16;
#pragma unroll
        for (int j = 0; j < 2; j++) {
            float v[8];
            if (node < n) {
                float4 f0 = __ldg((const float4*)(xr + j * 8));
                float4 f1 = __ldg((const float4*)(xr + j * 8) + 1);
                v[0] = f0.x; v[1] = f0.y; v[2] = f0.z; v[3] = f0.w;
                v[4] = f1.x; v[5] = f1.y; v[6] = f1.z; v[7] = f1.w;
            } else {
#pragma unroll
                for (int q = 0; q < 8; q++) v[q] = 0.f;
            }
            uint4 hi, lo;
            pack8(v, hi, lo);
            uint32_t byte = row * 64 + h * 32 + j * 16;
            uint32_t sw = byte ^ ((byte >> 3) & 0x30);
            *(uint4*)(smem + stageOff + sw) = hi;
            *(uint4*)(smem + stageOff + 8192 + sw) = lo;
        }
    } else {
        int rc = (c - 4) >> 2;                 // relation 0..4
        int qr = (c - 4) & 3;                  // quarter: cols qr*32..qr*32+31
        const unsigned char* agbase =
            g_AG + ((size_t)rc * NN_PAD + m0) * 512 + qr * 64;
        // 4 tiles x 512 units = 2048 units, 8/thread
#pragma unroll
        for (int i = 0; i < 8; i++) {
            int idx = tid + i * 256;
            int sub = idx >> 9, j = idx & 511;
            int row = j >> 2, s16 = j & 3;
            uint32_t byte = row * 64 + s16 * 16;
            uint32_t dstp = sbase + sub * 8192 + (byte ^ ((byte >> 3) & 0x30));
            const char* srcp;
            if (sub == 0)      srcp = (const char*)agbase + (size_t)row * 512 + s16 * 16;
            else if (sub == 1) srcp = (const char*)agbase + (size_t)row * 512 + 256 + s16 * 16;
            else if (sub == 2) srcp = (const char*)Bh + (size_t)row * 1536 + c * 64 + s16 * 16;
            else               srcp = (const char*)Bl + (size_t)row * 1536 + c * 64 + s16 * 16;
            asm volatile("cp.async.cg.shared.global [%0], [%1], 16;" :: "r"(dstp), "l"(srcp));
        }
        asm volatile("cp.async.commit_group;" ::: "memory");
    }
}
#endif  // HAS_TCGEN05

__global__ void __launch_bounds__(256, 2) k_mma(
    const float* __restrict__ X,
    const __nv_bfloat16* __restrict__ Bh, const __nv_bfloat16* __restrict__ Bl,
    const float* __restrict__ bias, float* __restrict__ Y, int n)
{
#if HAS_TCGEN05
    extern __shared__ char smem[];
    uint32_t sb = s2u(smem);
    int tid = threadIdx.x;
    int wid = tid >> 5, lane = tid & 31;
    int m0 = blockIdx.x * 128;

    if (wid == 0) {
        asm volatile(
            "tcgen05.alloc.cta_group::1.sync.aligned.shared::cta.b32 [%0], %1;"
            :: "r"(sb), "r"(128u) : "memory");
        asm volatile("tcgen05.relinquish_alloc_permit.cta_group::1.sync.aligned;");
    }
    if (tid == 0) {
        mbar_init(sb + 16, 1);
        mbar_init(sb + 24, 1);
        mbar_init(sb + 32, 1);
    }
    __syncthreads();
    uint32_t tmem;
    asm volatile("ld.shared.b32 %0, [%1];" : "=r"(tmem) : "r"(sb));

    load_chunk(0, smem, SMEM_TILES + 0 * STAGE_BYTES, m0, tid, X, Bh, Bl, n);
    load_chunk(1, smem, SMEM_TILES + 1 * STAGE_BYTES, m0, tid, X, Bh, Bl, n);

#pragma unroll 4
    for (int c = 0; c < NCHUNK; c++) {
        // 1) chunk c's data ready
        if (c <= NCHUNK - 2) asm volatile("cp.async.wait_group 1;" ::: "memory");
        else                 asm volatile("cp.async.wait_group 0;" ::: "memory");
        __syncthreads();
        // 2) issue MMA c
        if (tid == 0) {
            asm volatile("fence.proxy.async.shared::cta;" ::: "memory");
            uint32_t tb = sb + SMEM_TILES + (c % 3) * STAGE_BYTES;
            uint64_t dAh = sdesc64(tb);
            uint64_t dAl = sdesc64(tb + 8192);
            uint64_t dBh = sdesc64(tb + 16384);
            uint64_t dBl = sdesc64(tb + 24576);
#pragma unroll
            for (int ks = 0; ks < 2; ks++) {
                uint32_t e0 = (c == 0 && ks == 0) ? 0u : 1u;
                mma_f16_ss(tmem, dAh + ks * 2, dBh + ks * 2, MMA_IDESC, e0);
                mma_f16_ss(tmem, dAh + ks * 2, dBl + ks * 2, MMA_IDESC, 1u);
                mma_f16_ss(tmem, dAl + ks * 2, dBh + ks * 2, MMA_IDESC, 1u);
            }
            mma_commit(sb + 16 + (c % 3) * 8);
        }
        // 3) wait MMA c-1 (frees buffer (c+2)%3)
        if (c >= 1) {
            int t = c - 1;
            mbar_wait(sb + 16 + (t % 3) * 8, (t / 3) & 1);
        }
        // 4) loads for chunk c+2
        if (c + 2 < NCHUNK)
            load_chunk(c + 2, smem, SMEM_TILES + ((c + 2) % 3) * STAGE_BYTES,
                       m0, tid, X, Bh, Bl, n);
    }
    // final: chunk 23 commit is event 7 on mbar (23%3)=2 -> parity 1
    mbar_wait(sb + 32, (((NCHUNK - 1) / 3) & 1));
    asm volatile("tcgen05.fence::after_thread_sync;" ::: "memory");

    // ---- epilogue: TMEM -> bias+relu -> SMEM transpose -> coalesced f32 stores ----
    float* smF = (float*)(smem + SMEM_TILES);   // [128][129] f32 (66KB, fits)
    int sp = wid & 3, hh = wid >> 2;
#pragma unroll
    for (int p = 0; p < 2; p++) {
        uint32_t r[32];
        LDTM_X32(r, tmem + hh * 64 + p * 32);
        asm volatile("tcgen05.wait::ld.sync.aligned;" ::: "memory");
        int cb = hh * 64 + p * 32;
#pragma unroll
        for (int j = 0; j < 32; j++) {
            float v = __uint_as_float(r[j]) + __ldg(&bias[cb + j]);
            smF[(sp * 32 + lane) * 129 + cb + j] = fmaxf(v, 0.f);
        }
    }
    __syncthreads();
    for (int idx = tid; idx < 4096; idx += 256) {
        int row = idx >> 5, q = idx & 31;
        int grow = m0 + row;
        if (grow < n) {
            float* s = &smF[row * 129 + q * 4];
            float4 o;
            o.x = s[0]; o.y = s[1]; o.z = s[2]; o.w = s[3];
            *(float4*)(Y + (size_t)grow * 128 + q * 4) = o;
        }
    }
    __syncthreads();
    if (wid == 0) {
        asm volatile(
            "tcgen05.dealloc.cta_group::1.sync.aligned.b32 %0, %1;"
            :: "r"(tmem), "r"(128u));
    }
#else
    // ---- fallback (family-generic PTX pass; never used when sm_103a SASS loads) ----
    int tid = threadIdx.x;
    int m0 = blockIdx.x * 128;
    for (int o = tid; o < 128 * 128; o += 256) {
        int row = m0 + (o >> 7), col = o & 127;
        if (row >= n) continue;
        float acc = bias[col];
        for (int k = 0; k < 128; k++) {
            float b = __bfloat162float(Bh[(size_t)col * KTOT + k]) +
                      __bfloat162float(Bl[(size_t)col * KTOT + k]);
            acc += X[(size_t)row * 128 + k] * b;
        }
        for (int r = 0; r < NREL; r++) {
            const unsigned char* base = g_AG + ((size_t)r * NN_PAD + row) * 512;
            const __nv_bfloat16* ph = (const __nv_bfloat16*)base;
            const __nv_bfloat16* pl = (const __nv_bfloat16*)(base + 256);
            for (int k = 0; k < 128; k++) {
                float a = __bfloat162float(ph[k]) + __bfloat162float(pl[k]);
                float b = __bfloat162float(Bh[(size_t)col * KTOT + 128 + r * 128 + k]) +
                          __bfloat162float(Bl[(size_t)col * KTOT + 128 + r * 128 + k]);
                acc += a * b;
            }
        }
        Y[(size_t)row * 128 + col] = fmaxf(acc, 0.f);
    }
#endif
}

// ---------------- launch ----------------
extern "C" void kernel_launch(void* const* d_in, const int* in_sizes, int n_in,
                              void* d_out, int out_size) {
    const float* x  = (const float*)d_in[0];
    const int*   ei = (const int*)d_in[1];
    const int*   et = (const int*)d_in[2];
    const float* W1 = (const float*)d_in[3];
    const float* r1 = (const float*)d_in[4];
    const float* b1 = (const float*)d_in[5];
    const float* W2 = (const float*)d_in[6];
    const float* r2 = (const float*)d_in[7];
    const float* b2 = (const float*)d_in[8];
    const float* W3 = (const float*)d_in[9];
    const float* r3 = (const float*)d_in[10];
    const float* b3 = (const float*)d_in[11];
    float* out = (float*)d_out;

    int n = in_sizes[0] / F;
    int E = in_sizes[1] / 2;
    const int* src = ei;
    const int* dst = ei + E;
    int m = n * NREL;

    float *pB1, *pB2;
    __nv_bfloat16 *pBh, *pBl;
    cudaGetSymbolAddress((void**)&pB1, g_B1);
    cudaGetSymbolAddress((void**)&pB2, g_B2);
    cudaGetSymbolAddress((void**)&pBh, g_Bh);
    cudaGetSymbolAddress((void**)&pBl, g_Bl);

    static int smem_set = 0;
    if (!smem_set) {
        cudaFuncSetAttribute(k_mma, cudaFuncAttributeMaxDynamicSharedMemorySize, SMEM_TOTAL);
        smem_set = 1;
    }

    int gb = (m * 32 + 255) / 256;       // one warp per (node, rel) bucket
    int mb = (n + 127) / 128;

    k_csr<<<CSR_NB, 1024>>>(src, dst, et, E, m);
    k_prepB<<<(3 * BLAYER + 255) / 256, 256>>>(W1, r1, W2, r2, W3, r3);
    // layer 1  (k_mma is 4th launch -> ncu capture target)
    k_gather<<<gb, 256>>>(x, n);
    k_mma<<<mb, 256, SMEM_TOTAL>>>(x, pBh, pBl, b1, pB1, n);
    // layer 2
    k_gather<<<gb, 256>>>(pB1, n);
    k_mma<<<mb, 256, SMEM_TOTAL>>>(pB1, pBh + BLAYER, pBl + BLAYER, b2, pB2, n);
    // layer 3
    k_gather<<<gb, 256>>>(pB2, n);
    k_mma<<<mb, 256, SMEM_TOTAL>>>(pB2, pBh + 2 * BLAYER, pBl + 2 * BLAYER, b3, out, n);
}